// round 14
// baseline (speedup 1.0000x reference)
#include <cuda_runtime.h>

namespace {

typedef unsigned long long u64;

constexpr int ATOM   = 34;
constexpr int HID    = 256;
constexpr int LATENT = 128;
constexpr int CELLS  = 512;
constexpr int NN     = 128;
constexpr int XPAD   = 36;
constexpr int HALF   = 64;
constexpr int DIN    = LATENT + CELLS;
constexpr int NTHR   = 512;
constexpr int NWARP  = 16;
constexpr float NEGV = -9e15f;

#define FMA2(d, a, b, c) asm("fma.rn.f32x2 %0, %1, %2, %3;" : "=l"(d) : "l"(a), "l"(b), "l"(c))

__device__ __forceinline__ u64 pack2(float lo, float hi) {
    u64 r; asm("mov.b64 %0, {%1, %2};" : "=l"(r) : "f"(lo), "f"(hi)); return r;
}
__device__ __forceinline__ float2 unpack2(u64 v) {
    float lo, hi; asm("mov.b64 {%0, %1}, %2;" : "=f"(lo), "=f"(hi) : "l"(v));
    return make_float2(lo, hi);
}
union F4U2 { float4 f4; struct { u64 lo, hi; } u; };

struct __align__(16) Smem {
    alignas(16) float2 WgP[3][17][32];     // (Wg[2k][l], Wg[2k+1][l])
    float Wgc[3][ATOM][2];                 // Wg columns 32,33
    float bg[3][ATOM];
    float attnv[3][2 * ATOM];
    alignas(16) float Wt[ATOM][HID];
    alignas(16) float bt[HID];
    alignas(16) float4 WfQ[HID / 4][32];   // (Wf[4p..4p+3][l])
    alignas(16) float Wfc32[HID];
    alignas(16) float Wfc33[HID];
    float bf[ATOM];
    alignas(16) float Wf2[ATOM][LATENT];
    alignas(16) float bf2[LATENT];
    alignas(16) float x[NN][XPAD];         // own rows updated in place (never peer-read)
    float xs0[HALF][ATOM];
    alignas(16) float hb[2][NN][XPAD];     // h, double-buffered by round parity
    float fsrc[2][NN];                     // round-parity buffered
    float fdst[2][NN];
    alignas(16) unsigned mask[HALF][4];
    union alignas(16) U {
        float attbuf[NWARP][NN][4];
        float gbuf[NWARP][2][HID];
    } u;
    alignas(16) float dvbuf[NWARP][2][36];
    alignas(16) float wmax[NWARP][LATENT];  // also MLP partial buffer
    float latloc[LATENT];
    float latpeer[LATENT];
    float vec[DIN];
    alignas(16) float h1[128];
    alignas(16) float h2[256];
    alignas(16) float h3own[256];
    float red[NWARP];
    float partial4;                         // written ONLY by rank1 via DSMEM
};

__device__ __forceinline__ float warp_sum(float v) {
    #pragma unroll
    for (int off = 16; off; off >>= 1)
        v += __shfl_xor_sync(0xffffffffu, v, off);
    return v;
}
__device__ __forceinline__ unsigned smem_u32(const void* p) {
    return (unsigned)__cvta_generic_to_shared(p);
}
__device__ __forceinline__ unsigned mapa_peer(unsigned local, unsigned rank) {
    unsigned r;
    asm("mapa.shared::cluster.u32 %0, %1, %2;" : "=r"(r) : "r"(local), "r"(rank));
    return r;
}
__device__ __forceinline__ void st_cluster_f32(unsigned addr, float v) {
    asm volatile("st.shared::cluster.f32 [%0], %1;" :: "r"(addr), "f"(v) : "memory");
}
__device__ __forceinline__ void st_cluster_u64(unsigned addr, u64 v) {
    asm volatile("st.shared::cluster.b64 [%0], %1;" :: "r"(addr), "l"(v) : "memory");
}
__device__ __forceinline__ void cluster_sync_() {
    asm volatile("barrier.cluster.arrive.aligned;" ::: "memory");
    asm volatile("barrier.cluster.wait.aligned;" ::: "memory");
}
__device__ __forceinline__ unsigned ctarank() {
    unsigned r;
    asm("mov.u32 %0, %%cluster_ctarank;" : "=r"(r));
    return r;
}

__global__ void __launch_bounds__(NTHR, 1) __cluster_dims__(2, 1, 1)
disease_kernel(const float* __restrict__ xs, const int* __restrict__ A,
               const float* __restrict__ cell,
               const float* __restrict__ Wg_g, const float* __restrict__ bg_g,
               const float* __restrict__ attn_g,
               const float* __restrict__ Wt_g, const float* __restrict__ bt_g,
               const float* __restrict__ Wf_g, const float* __restrict__ bf_g,
               const float* __restrict__ Wf2_g, const float* __restrict__ bf2_g,
               const float* __restrict__ W1, const float* __restrict__ b1,
               const float* __restrict__ W2, const float* __restrict__ b2,
               const float* __restrict__ W3, const float* __restrict__ b3,
               const float* __restrict__ W4, const float* __restrict__ b4,
               float* __restrict__ out)
{
    extern __shared__ char smem_raw[];
    Smem& s = *reinterpret_cast<Smem*>(smem_raw);
    const int b     = blockIdx.x >> 1;
    const unsigned rank = ctarank();
    const unsigned prk  = rank ^ 1u;
    const int own0  = (int)rank * HALF;
    const int tid   = threadIdx.x;
    const int lane  = tid & 31;
    const int w     = tid >> 5;

    const unsigned peer_h0  = mapa_peer(smem_u32(&s.hb[0][0][0]), prk);
    const unsigned peer_h1b = mapa_peer(smem_u32(&s.hb[1][0][0]), prk);
    const unsigned peer_fs0 = mapa_peer(smem_u32(&s.fsrc[0][0]), prk);
    const unsigned peer_fs1 = mapa_peer(smem_u32(&s.fsrc[1][0]), prk);
    const unsigned peer_fd0 = mapa_peer(smem_u32(&s.fdst[0][0]), prk);
    const unsigned peer_fd1 = mapa_peer(smem_u32(&s.fdst[1][0]), prk);
    const unsigned peer_lat = mapa_peer(smem_u32(&s.latpeer[0]), prk);

    // ---------- stage weights + inputs ----------
    for (int i = tid; i < 3 * 17 * 32; i += NTHR) {
        int r = i / (17 * 32), rem = i % (17 * 32), k = rem >> 5, l = rem & 31;
        s.WgP[r][k][l] = make_float2(Wg_g[r * ATOM * ATOM + (2 * k) * ATOM + l],
                                     Wg_g[r * ATOM * ATOM + (2 * k + 1) * ATOM + l]);
    }
    for (int i = tid; i < 3 * ATOM * 2; i += NTHR) {
        int r = i / (ATOM * 2), rem = i % (ATOM * 2), d = rem >> 1, c = rem & 1;
        s.Wgc[r][d][c] = Wg_g[r * ATOM * ATOM + d * ATOM + 32 + c];
    }
    for (int i = tid; i < 3 * ATOM; i += NTHR)        (&s.bg[0][0])[i]    = bg_g[i];
    for (int i = tid; i < 3 * 2 * ATOM; i += NTHR)    (&s.attnv[0][0])[i] = attn_g[i];
    for (int i = tid; i < (ATOM * HID) / 4; i += NTHR)
        reinterpret_cast<float4*>(&s.Wt[0][0])[i] =
            reinterpret_cast<const float4*>(Wt_g)[i];
    for (int i = tid; i < HID; i += NTHR)             s.bt[i]             = bt_g[i];
    for (int i = tid; i < (HID / 4) * 32; i += NTHR) {
        int p = i >> 5, l = i & 31;
        s.WfQ[p][l] = make_float4(Wf_g[(4 * p) * ATOM + l], Wf_g[(4 * p + 1) * ATOM + l],
                                  Wf_g[(4 * p + 2) * ATOM + l], Wf_g[(4 * p + 3) * ATOM + l]);
    }
    for (int i = tid; i < HID; i += NTHR) {
        s.Wfc32[i] = Wf_g[i * ATOM + 32];
        s.Wfc33[i] = Wf_g[i * ATOM + 33];
    }
    for (int i = tid; i < ATOM; i += NTHR)            s.bf[i]             = bf_g[i];
    for (int i = tid; i < (ATOM * LATENT) / 4; i += NTHR)
        reinterpret_cast<float4*>(&s.Wf2[0][0])[i] =
            reinterpret_cast<const float4*>(Wf2_g)[i];
    for (int i = tid; i < LATENT; i += NTHR)          s.bf2[i]            = bf2_g[i];
    for (int i = tid; i < NN * ATOM; i += NTHR) {
        int n = i / ATOM, d = i % ATOM;
        float v = xs[((size_t)b * NN + n) * ATOM + d];
        s.x[n][d] = v;
        if (n >= own0 && n < own0 + HALF) s.xs0[n - own0][d] = v;
    }

    // ---------- adjacency bitmask (own 64 rows) ----------
    {
        const int* __restrict__ Abase = A + (size_t)b * NN * NN;
        #pragma unroll
        for (int t = 0; t < 16; t++) {
            int widx  = w * 16 + t;
            int row   = widx >> 2;
            int chunk = widx & 3;
            int q     = chunk * 32 + lane;
            int av    = Abase[(own0 + row) * NN + q];
            unsigned word = __ballot_sync(0xffffffffu, av > 0);
            if (lane == 0) s.mask[row][chunk] = word;
        }
    }
    __syncthreads();

    // ---------- 3 GAT rounds; x in place, h/f parity-buffered ----------
    for (int r = 0; r < 3; r++) {
        const int par = r & 1;
        float (*hc)[XPAD] = s.hb[par];
        float* fsc = s.fsrc[par];
        float* fdc = s.fdst[par];
        const unsigned ph  = par ? peer_h1b : peer_h0;
        const unsigned pfs = par ? peer_fs1 : peer_fs0;
        const unsigned pfd = par ? peer_fd1 : peer_fd0;

        // h = relu(x @ Wg + bg): warp computes 4 OWN rows; mirror to peer.
        {
            u64 wgp[17];
            #pragma unroll
            for (int k = 0; k < 17; k++)
                wgp[k] = *reinterpret_cast<const u64*>(&s.WgP[r][k][lane]);
            const float bgl = s.bg[r][lane];
            const int n0 = own0 + 4 * w;
            #pragma unroll
            for (int j = 0; j < 4; j++) {
                const int n = n0 + j;
                u64 acc0 = pack2(bgl, 0.f);
                u64 acc1 = 0ull;
                #pragma unroll
                for (int db = 0; db < 8; db++) {
                    F4U2 xv; xv.f4 = *reinterpret_cast<const float4*>(&s.x[n][4 * db]);
                    FMA2(acc0, xv.u.lo, wgp[2 * db],     acc0);
                    FMA2(acc1, xv.u.hi, wgp[2 * db + 1], acc1);
                }
                u64 x2 = *reinterpret_cast<const u64*>(&s.x[n][32]);
                FMA2(acc0, x2, wgp[16], acc0);
                float2 a = unpack2(acc0), c = unpack2(acc1);
                float hv = fmaxf((a.x + a.y) + (c.x + c.y), 0.f);
                hc[n][lane] = hv;
                st_cluster_f32(ph + (unsigned)(n * XPAD + lane) * 4u, hv);
            }
        }
        // columns 32,33 mini-pass: own 64 rows (128 threads), mirrored
        if (tid < 128) {
            const int n = own0 + (tid >> 1), e = tid & 1;
            float a0 = s.bg[r][32 + e], a1 = 0.f;
            #pragma unroll
            for (int d = 0; d < ATOM; d += 2) {
                a0 += s.x[n][d]     * s.Wgc[r][d][e];
                a1 += s.x[n][d + 1] * s.Wgc[r][d + 1][e];
            }
            float hv = fmaxf(a0 + a1, 0.f);
            hc[n][32 + e] = hv;
            st_cluster_f32(ph + (unsigned)(n * XPAD + 32 + e) * 4u, hv);
        }
        __syncthreads();   // local h complete (fsrc below reads own-row h locally)

        // fsrc/fdst: own 64 rows (128 threads), mirrored
        if (tid < 128) {
            const int n = own0 + (tid >> 1), side = tid & 1;
            const float* av = &s.attnv[r][side * ATOM];
            float a0 = 0.f, a1 = 0.f;
            #pragma unroll
            for (int e = 0; e < ATOM; e += 2) {
                a0 += hc[n][e]     * av[e];
                a1 += hc[n][e + 1] * av[e + 1];
            }
            float fv = a0 + a1;
            if (side) {
                fdc[n] = fv;
                st_cluster_f32(pfd + (unsigned)n * 4u, fv);
            } else {
                fsc[n] = fv;
                st_cluster_f32(pfs + (unsigned)n * 4u, fv);
            }
        }
        // the ONLY cluster barrier this round: peer h + f delivered
        cluster_sync_();

        // softmax: 4 own rows per warp; no max-subtraction (exp-safe range),
        // masked entries exp(NEGV) underflow to exactly 0 as in reference.
        {
            float sc[4][4];
            #pragma unroll
            for (int rr = 0; rr < 4; rr++) {
                const int pl = w + 16 * rr;                 // local row
                const float fs = fsc[own0 + pl];
                uint4 mr = *reinterpret_cast<const uint4*>(&s.mask[pl][0]);
                const unsigned mw[4] = {mr.x, mr.y, mr.z, mr.w};
                #pragma unroll
                for (int j = 0; j < 4; j++) {
                    float e = fs + fdc[lane + 32 * j];
                    e = e > 0.f ? e : 0.01f * e;            // leaky_relu(0.01)
                    sc[rr][j] = ((mw[j] >> lane) & 1u) ? e : NEGV;
                }
            }
            float sum[4];
            #pragma unroll
            for (int rr = 0; rr < 4; rr++) {
                sum[rr] = 0.f;
                #pragma unroll
                for (int j = 0; j < 4; j++) {
                    sc[rr][j] = __expf(sc[rr][j]);          // reuse sc as weights
                    sum[rr] += sc[rr][j];
                }
            }
            #pragma unroll
            for (int off = 16; off; off >>= 1) {
                #pragma unroll
                for (int rr = 0; rr < 4; rr++)
                    sum[rr] += __shfl_xor_sync(0xffffffffu, sum[rr], off);
            }
            float inv[4];
            #pragma unroll
            for (int rr = 0; rr < 4; rr++) inv[rr] = 1.f / sum[rr];
            #pragma unroll
            for (int j = 0; j < 4; j++) {
                *reinterpret_cast<float4*>(&s.u.attbuf[w][lane + 32 * j][0]) =
                    make_float4(sc[0][j] * inv[0], sc[1][j] * inv[1],
                                sc[2][j] * inv[2], sc[3][j] * inv[3]);
            }
        }
        __syncwarp();

        // msg[d=lane] for 4 rows, f32x2, 4 accumulator chains
        u64 macc0 = 0ull, macc1 = 0ull, macc2 = 0ull, macc3 = 0ull;
        #pragma unroll 8
        for (int q = 0; q < NN; q += 2) {
            float hv0 = hc[q][lane];
            float hv1 = hc[q + 1][lane];
            F4U2 a0; a0.f4 = *reinterpret_cast<const float4*>(&s.u.attbuf[w][q][0]);
            F4U2 a1; a1.f4 = *reinterpret_cast<const float4*>(&s.u.attbuf[w][q + 1][0]);
            u64 hp0 = pack2(hv0, hv0), hp1 = pack2(hv1, hv1);
            FMA2(macc0, a0.u.lo, hp0, macc0);
            FMA2(macc1, a0.u.hi, hp0, macc1);
            FMA2(macc2, a1.u.lo, hp1, macc2);
            FMA2(macc3, a1.u.hi, hp1, macc3);
        }
        float2 mlo0 = unpack2(macc0), mhi0 = unpack2(macc1);
        float2 mlo1 = unpack2(macc2), mhi1 = unpack2(macc3);
        float m0[4] = {mlo0.x + mlo1.x, mlo0.y + mlo1.y,
                       mhi0.x + mhi1.x, mhi0.y + mhi1.y};

        // dims 32,33 partials — ONE interleaved 8-value warp reduction
        float mm[8] = {0.f, 0.f, 0.f, 0.f, 0.f, 0.f, 0.f, 0.f};
        #pragma unroll
        for (int j = 0; j < 4; j++) {
            int q = lane + 32 * j;
            float h32 = hc[q][32], h33 = hc[q][33];
            float4 a = *reinterpret_cast<const float4*>(&s.u.attbuf[w][q][0]);
            mm[0] += a.x * h32; mm[1] += a.y * h32; mm[2] += a.z * h32; mm[3] += a.w * h32;
            mm[4] += a.x * h33; mm[5] += a.y * h33; mm[6] += a.z * h33; mm[7] += a.w * h33;
        }
        #pragma unroll
        for (int off = 16; off; off >>= 1) {
            #pragma unroll
            for (int i = 0; i < 8; i++)
                mm[i] += __shfl_xor_sync(0xffffffffu, mm[i], off);
        }
        // in-place x update: own rows only (x is never read by the peer CTA)
        #pragma unroll
        for (int rr = 0; rr < 4; rr++) {
            const int p = own0 + w + 16 * rr;
            s.x[p][lane] += m0[rr];
            if (lane == 0) {
                s.x[p][32] += mm[rr];
                s.x[p][33] += mm[4 + rr];
            }
        }
        __syncthreads();   // local x updates visible CTA-wide for next round
    }

    // ---------- readout: 4 own rows per warp, 2 at a time, f32x2 ----------
    float rmax[4] = {-3.4e38f, -3.4e38f, -3.4e38f, -3.4e38f};
    const int rbase = own0 + 4 * w;
    #pragma unroll
    for (int bt2 = 0; bt2 < 2; bt2++) {
        const int rA = rbase + 2 * bt2;
        const int rB = rA + 1;
        const int e0 = 8 * lane;

        // g = relu(x@Wt+bt), 2 rows, lane owns 8 e's as 4 pairs
        u64 gAp[4], gBp[4];
        #pragma unroll
        for (int k = 0; k < 4; k++) {
            u64 btp = *reinterpret_cast<const u64*>(&s.bt[e0 + 2 * k]);
            gAp[k] = btp; gBp[k] = btp;
        }
        #pragma unroll
        for (int db = 0; db < 8; db++) {
            const int d = 4 * db;
            float4 xA = *reinterpret_cast<const float4*>(&s.x[rA][d]);
            float4 xB = *reinterpret_cast<const float4*>(&s.x[rB][d]);
            #pragma unroll
            for (int dd = 0; dd < 4; dd++) {
                F4U2 w0; w0.f4 = *reinterpret_cast<const float4*>(&s.Wt[d + dd][e0]);
                F4U2 w1; w1.f4 = *reinterpret_cast<const float4*>(&s.Wt[d + dd][e0 + 4]);
                u64 xap = pack2((&xA.x)[dd], (&xA.x)[dd]);
                u64 xbp = pack2((&xB.x)[dd], (&xB.x)[dd]);
                FMA2(gAp[0], w0.u.lo, xap, gAp[0]);
                FMA2(gAp[1], w0.u.hi, xap, gAp[1]);
                FMA2(gAp[2], w1.u.lo, xap, gAp[2]);
                FMA2(gAp[3], w1.u.hi, xap, gAp[3]);
                FMA2(gBp[0], w0.u.lo, xbp, gBp[0]);
                FMA2(gBp[1], w0.u.hi, xbp, gBp[1]);
                FMA2(gBp[2], w1.u.lo, xbp, gBp[2]);
                FMA2(gBp[3], w1.u.hi, xbp, gBp[3]);
            }
        }
        {
            float2 xA2 = *reinterpret_cast<const float2*>(&s.x[rA][32]);
            float2 xB2 = *reinterpret_cast<const float2*>(&s.x[rB][32]);
            #pragma unroll
            for (int dd = 0; dd < 2; dd++) {
                F4U2 w0; w0.f4 = *reinterpret_cast<const float4*>(&s.Wt[32 + dd][e0]);
                F4U2 w1; w1.f4 = *reinterpret_cast<const float4*>(&s.Wt[32 + dd][e0 + 4]);
                float xa = dd ? xA2.y : xA2.x;
                float xb = dd ? xB2.y : xB2.x;
                u64 xap = pack2(xa, xa), xbp = pack2(xb, xb);
                FMA2(gAp[0], w0.u.lo, xap, gAp[0]);
                FMA2(gAp[1], w0.u.hi, xap, gAp[1]);
                FMA2(gAp[2], w1.u.lo, xap, gAp[2]);
                FMA2(gAp[3], w1.u.hi, xap, gAp[3]);
                FMA2(gBp[0], w0.u.lo, xbp, gBp[0]);
                FMA2(gBp[1], w0.u.hi, xbp, gBp[1]);
                FMA2(gBp[2], w1.u.lo, xbp, gBp[2]);
                FMA2(gBp[3], w1.u.hi, xbp, gBp[3]);
            }
        }
        #pragma unroll
        for (int k = 0; k < 4; k++) {
            float2 ga = unpack2(gAp[k]);
            float2 gb = unpack2(gBp[k]);
            ga.x = fmaxf(ga.x, 0.f); ga.y = fmaxf(ga.y, 0.f);
            gb.x = fmaxf(gb.x, 0.f); gb.y = fmaxf(gb.y, 0.f);
            gAp[k] = pack2(ga.x, ga.y);
            gBp[k] = pack2(gb.x, gb.y);
            *reinterpret_cast<u64*>(&s.u.gbuf[w][0][e0 + 2 * k]) = gAp[k];
            *reinterpret_cast<u64*>(&s.u.gbuf[w][1][e0 + 2 * k]) = gBp[k];
        }
        __syncwarp();

        // dv[lane] = sum_e g[e]*Wf[e][lane], 2 rows, quad-packed Wf
        u64 dA0 = 0ull, dA1 = 0ull, dB0 = 0ull, dB1 = 0ull;
        #pragma unroll 8
        for (int e = 0; e < HID; e += 4) {
            F4U2 wf; wf.f4 = s.WfQ[e >> 2][lane];
            F4U2 ga; ga.f4 = *reinterpret_cast<const float4*>(&s.u.gbuf[w][0][e]);
            F4U2 gb; gb.f4 = *reinterpret_cast<const float4*>(&s.u.gbuf[w][1][e]);
            FMA2(dA0, ga.u.lo, wf.u.lo, dA0);
            FMA2(dA1, ga.u.hi, wf.u.hi, dA1);
            FMA2(dB0, gb.u.lo, wf.u.lo, dB0);
            FMA2(dB1, gb.u.hi, wf.u.hi, dB1);
        }
        float2 a0 = unpack2(dA0), a1 = unpack2(dA1);
        float2 c0 = unpack2(dB0), c1 = unpack2(dB1);
        float dvA = s.bf[lane] + s.xs0[rA - own0][lane] + ((a0.x + a0.y) + (a1.x + a1.y));
        float dvB = s.bf[lane] + s.xs0[rB - own0][lane] + ((c0.x + c0.y) + (c1.x + c1.y));

        // d[32], d[33] partials from register g (f32x2) — interleaved 4-sum
        u64 aA32 = 0ull, aA33 = 0ull, aB32 = 0ull, aB33 = 0ull;
        {
            F4U2 c32a; c32a.f4 = *reinterpret_cast<const float4*>(&s.Wfc32[e0]);
            F4U2 c32b; c32b.f4 = *reinterpret_cast<const float4*>(&s.Wfc32[e0 + 4]);
            F4U2 c33a; c33a.f4 = *reinterpret_cast<const float4*>(&s.Wfc33[e0]);
            F4U2 c33b; c33b.f4 = *reinterpret_cast<const float4*>(&s.Wfc33[e0 + 4]);
            u64 c32p[4] = {c32a.u.lo, c32a.u.hi, c32b.u.lo, c32b.u.hi};
            u64 c33p[4] = {c33a.u.lo, c33a.u.hi, c33b.u.lo, c33b.u.hi};
            #pragma unroll
            for (int k = 0; k < 4; k++) {
                FMA2(aA32, gAp[k], c32p[k], aA32);
                FMA2(aA33, gAp[k], c33p[k], aA33);
                FMA2(aB32, gBp[k], c32p[k], aB32);
                FMA2(aB33, gBp[k], c33p[k], aB33);
            }
        }
        float2 tA32 = unpack2(aA32), tA33 = unpack2(aA33);
        float2 tB32 = unpack2(aB32), tB33 = unpack2(aB33);
        float pA32 = tA32.x + tA32.y, pA33 = tA33.x + tA33.y;
        float pB32 = tB32.x + tB32.y, pB33 = tB33.x + tB33.y;
        #pragma unroll
        for (int off = 16; off; off >>= 1) {
            pA32 += __shfl_xor_sync(0xffffffffu, pA32, off);
            pA33 += __shfl_xor_sync(0xffffffffu, pA33, off);
            pB32 += __shfl_xor_sync(0xffffffffu, pB32, off);
            pB33 += __shfl_xor_sync(0xffffffffu, pB33, off);
        }
        s.dvbuf[w][0][lane] = dvA;
        s.dvbuf[w][1][lane] = dvB;
        if (lane == 0) {
            s.dvbuf[w][0][32] = pA32 + s.bf[32] + s.xs0[rA - own0][32];
            s.dvbuf[w][0][33] = pA33 + s.bf[33] + s.xs0[rA - own0][33];
            s.dvbuf[w][1][32] = pB32 + s.bf[32] + s.xs0[rB - own0][32];
            s.dvbuf[w][1][33] = pB33 + s.bf[33] + s.xs0[rB - own0][33];
        }
        __syncwarp();

        // latent = dv @ Wf2 + bf2, lane owns 4 latents (2 pairs), 2 rows
        {
            const int l0 = 4 * lane;
            u64 accA0 = *reinterpret_cast<const u64*>(&s.bf2[l0]);
            u64 accA1 = *reinterpret_cast<const u64*>(&s.bf2[l0 + 2]);
            u64 accB0 = accA0, accB1 = accA1;
            #pragma unroll
            for (int db = 0; db < 8; db++) {
                const int d = 4 * db;
                float4 dA4 = *reinterpret_cast<const float4*>(&s.dvbuf[w][0][d]);
                float4 dB4 = *reinterpret_cast<const float4*>(&s.dvbuf[w][1][d]);
                #pragma unroll
                for (int dd = 0; dd < 4; dd++) {
                    F4U2 wv; wv.f4 = *reinterpret_cast<const float4*>(&s.Wf2[d + dd][l0]);
                    u64 dap = pack2((&dA4.x)[dd], (&dA4.x)[dd]);
                    u64 dbp = pack2((&dB4.x)[dd], (&dB4.x)[dd]);
                    FMA2(accA0, wv.u.lo, dap, accA0);
                    FMA2(accA1, wv.u.hi, dap, accA1);
                    FMA2(accB0, wv.u.lo, dbp, accB0);
                    FMA2(accB1, wv.u.hi, dbp, accB1);
                }
            }
            {
                float2 dA2 = *reinterpret_cast<const float2*>(&s.dvbuf[w][0][32]);
                float2 dB2 = *reinterpret_cast<const float2*>(&s.dvbuf[w][1][32]);
                F4U2 w32; w32.f4 = *reinterpret_cast<const float4*>(&s.Wf2[32][l0]);
                F4U2 w33; w33.f4 = *reinterpret_cast<const float4*>(&s.Wf2[33][l0]);
                u64 a32p = pack2(dA2.x, dA2.x), a33p = pack2(dA2.y, dA2.y);
                u64 b32p = pack2(dB2.x, dB2.x), b33p = pack2(dB2.y, dB2.y);
                FMA2(accA0, w32.u.lo, a32p, accA0);
                FMA2(accA1, w32.u.hi, a32p, accA1);
                FMA2(accA0, w33.u.lo, a33p, accA0);
                FMA2(accA1, w33.u.hi, a33p, accA1);
                FMA2(accB0, w32.u.lo, b32p, accB0);
                FMA2(accB1, w32.u.hi, b32p, accB1);
                FMA2(accB0, w33.u.lo, b33p, accB0);
                FMA2(accB1, w33.u.hi, b33p, accB1);
            }
            float2 rA0 = unpack2(accA0), rA1 = unpack2(accA1);
            float2 rB0 = unpack2(accB0), rB1 = unpack2(accB1);
            rmax[0] = fmaxf(rmax[0], fmaxf(rA0.x, rB0.x));
            rmax[1] = fmaxf(rmax[1], fmaxf(rA0.y, rB0.y));
            rmax[2] = fmaxf(rmax[2], fmaxf(rA1.x, rB1.x));
            rmax[3] = fmaxf(rmax[3], fmaxf(rA1.y, rB1.y));
        }
        __syncwarp();
    }
    #pragma unroll
    for (int j = 0; j < 4; j++) s.wmax[w][4 * lane + j] = rmax[j];
    __syncthreads();

    // ---------- row-max combine + cluster exchange ----------
    if (tid < LATENT) {
        float m = s.wmax[0][tid];
        #pragma unroll
        for (int ww = 1; ww < NWARP; ww++) m = fmaxf(m, s.wmax[ww][tid]);
        s.latloc[tid] = m;
        st_cluster_f32(peer_lat + (unsigned)tid * 4u, m);
    }
    cluster_sync_();

    if (tid < LATENT) {
        float m = fmaxf(s.latloc[tid], s.latpeer[tid]);
        s.vec[tid] = 1.f / (1.f + __expf(-m));
    }
    for (int j = tid; j < CELLS; j += NTHR) {
        float c = cell[(size_t)b * CELLS + j];
        s.vec[LATENT + j] = 1.f / (1.f + __expf(-c));
    }
    __syncthreads();

    const unsigned peer_p4 = mapa_peer(smem_u32(&s.partial4), prk);
    float* wflat = &s.wmax[0][0];

    // ---------- MLP L1: 640 -> 128 FULL per CTA (no cluster split/sync) ----------
    {
        const int o2 = tid & 63, part = tid >> 6;   // 64 pairs = 128 outs, 8 parts x 80 k
        const int k0 = part * 80;
        u64 acc0 = 0ull, acc1 = 0ull, acc2 = 0ull, acc3 = 0ull;
        #pragma unroll 2
        for (int k = k0; k < k0 + 80; k += 4) {
            F4U2 vv; vv.f4 = *reinterpret_cast<const float4*>(&s.vec[k]);
            float2 vlo = unpack2(vv.u.lo), vhi = unpack2(vv.u.hi);
            u64 w0 = *reinterpret_cast<const u64*>(&W1[(size_t)k * 128 + 2 * o2]);
            u64 w1 = *reinterpret_cast<const u64*>(&W1[(size_t)(k + 1) * 128 + 2 * o2]);
            u64 w2 = *reinterpret_cast<const u64*>(&W1[(size_t)(k + 2) * 128 + 2 * o2]);
            u64 w3 = *reinterpret_cast<const u64*>(&W1[(size_t)(k + 3) * 128 + 2 * o2]);
            FMA2(acc0, w0, pack2(vlo.x, vlo.x), acc0);
            FMA2(acc1, w1, pack2(vlo.y, vlo.y), acc1);
            FMA2(acc2, w2, pack2(vhi.x, vhi.x), acc2);
            FMA2(acc3, w3, pack2(vhi.y, vhi.y), acc3);
        }
        float2 p0 = unpack2(acc0), p1 = unpack2(acc1);
        float2 p2 = unpack2(acc2), p3 = unpack2(acc3);
        *reinterpret_cast<float2*>(&wflat[part * 128 + 2 * o2]) =
            make_float2((p0.x + p1.x) + (p2.x + p3.x),
                        (p0.y + p1.y) + (p2.y + p3.y));
    }
    __syncthreads();
    if (tid < 64) {
        float2 v = *reinterpret_cast<const float2*>(&wflat[2 * tid]);
        #pragma unroll
        for (int p = 1; p < 8; p++) {
            float2 t = *reinterpret_cast<const float2*>(&wflat[p * 128 + 2 * tid]);
            v.x += t.x; v.y += t.y;
        }
        v.x = fmaxf(v.x + b1[2 * tid], 0.f);
        v.y = fmaxf(v.y + b1[2 * tid + 1], 0.f);
        *reinterpret_cast<float2*>(&s.h1[2 * tid]) = v;
    }
    __syncthreads();

    // ---------- MLP L2: 128 -> 256 FULL per CTA ----------
    {
        const int o2 = tid & 127, part = tid >> 7;  // 128 pairs = 256 outs, 4 parts x 32 k
        const int k0 = part * 32;
        u64 acc0 = 0ull, acc1 = 0ull;
        #pragma unroll 4
        for (int k = k0; k < k0 + 32; k += 2) {
            u64 w0 = *reinterpret_cast<const u64*>(&W2[(size_t)k * 256 + 2 * o2]);
            u64 w1 = *reinterpret_cast<const u64*>(&W2[(size_t)(k + 1) * 256 + 2 * o2]);
            FMA2(acc0, w0, pack2(s.h1[k], s.h1[k]), acc0);
            FMA2(acc1, w1, pack2(s.h1[k + 1], s.h1[k + 1]), acc1);
        }
        float2 p0 = unpack2(acc0), p1 = unpack2(acc1);
        *reinterpret_cast<float2*>(&wflat[part * 256 + 2 * o2]) =
            make_float2(p0.x + p1.x, p0.y + p1.y);
    }
    __syncthreads();
    if (tid < 128) {
        float2 v = *reinterpret_cast<const float2*>(&wflat[2 * tid]);
        #pragma unroll
        for (int p = 1; p < 4; p++) {
            float2 t = *reinterpret_cast<const float2*>(&wflat[p * 256 + 2 * tid]);
            v.x += t.x; v.y += t.y;
        }
        v.x = fmaxf(v.x + b2[2 * tid], 0.f);
        v.y = fmaxf(v.y + b2[2 * tid + 1], 0.f);
        *reinterpret_cast<float2*>(&s.h2[2 * tid]) = v;
    }
    __syncthreads();

    // ---------- MLP L3: 256 -> 512, SPLIT (own 256 outs), from local full h2 ----------
    {
        const int o2 = tid & 127, part = tid >> 7;
        const int og2 = (int)rank * 128 + o2;
        const int k0 = part * 64;
        u64 acc0 = 0ull, acc1 = 0ull;
        #pragma unroll 4
        for (int k = k0; k < k0 + 64; k += 2) {
            u64 w0 = *reinterpret_cast<const u64*>(&W3[(size_t)k * 512 + 2 * og2]);
            u64 w1 = *reinterpret_cast<const u64*>(&W3[(size_t)(k + 1) * 512 + 2 * og2]);
            FMA2(acc0, w0, pack2(s.h2[k], s.h2[k]), acc0);
            FMA2(acc1, w1, pack2(s.h2[k + 1], s.h2[k + 1]), acc1);
        }
        float2 p0 = unpack2(acc0), p1 = unpack2(acc1);
        *reinterpret_cast<float2*>(&wflat[part * 256 + 2 * o2]) =
            make_float2(p0.x + p1.x, p0.y + p1.y);
    }
    __syncthreads();
    if (tid < 128) {
        float2 v = *reinterpret_cast<const float2*>(&wflat[2 * tid]);
        #pragma unroll
        for (int p = 1; p < 4; p++) {
            float2 t = *reinterpret_cast<const float2*>(&wflat[p * 256 + 2 * tid]);
            v.x += t.x; v.y += t.y;
        }
        const int og = (int)rank * 256 + 2 * tid;
        v.x = fmaxf(v.x + b3[og], 0.f);
        v.y = fmaxf(v.y + b3[og + 1], 0.f);
        *reinterpret_cast<float2*>(&s.h3own[2 * tid]) = v;
    }
    __syncthreads();

    // ---------- MLP L4: 512 -> 1 (split dot, rank1 -> rank0 via DSMEM) ----------
    {
        float acc = 0.f;
        if (tid < 256) acc = s.h3own[tid] * W4[(int)rank * 256 + tid];
        acc = warp_sum(acc);
        if (lane == 0) s.red[w] = acc;
    }
    __syncthreads();
    if (rank == 1 && tid == 0) {
        float acc = 0.f;
        #pragma unroll
        for (int ww = 0; ww < 8; ww++) acc += s.red[ww];
        st_cluster_f32(peer_p4, acc);
    }
    cluster_sync_();
    if (rank == 0 && tid == 0) {
        float acc = 0.f;
        #pragma unroll
        for (int ww = 0; ww < 8; ww++) acc += s.red[ww];
        out[b] = acc + s.partial4 + b4[0];
    }
}

} // namespace

extern "C" void kernel_launch(void* const* d_in, const int* in_sizes, int n_in,
                              void* d_out, int out_size) {
    (void)in_sizes; (void)n_in; (void)out_size;
    const float* xs   = (const float*)d_in[0];
    const int*   A    = (const int*)d_in[1];
    const float* cell = (const float*)d_in[2];
    const float* Wg   = (const float*)d_in[3];
    const float* bg   = (const float*)d_in[4];
    const float* attn = (const float*)d_in[5];
    const float* Wt   = (const float*)d_in[6];
    const float* bt   = (const float*)d_in[7];
    const float* Wf   = (const float*)d_in[8];
    const float* bf   = (const float*)d_in[9];
    const float* Wf2  = (const float*)d_in[10];
    const float* bf2  = (const float*)d_in[11];
    const float* W1   = (const float*)d_in[12];
    const float* b1   = (const float*)d_in[13];
    const float* W2   = (const float*)d_in[14];
    const float* b2   = (const float*)d_in[15];
    const float* W3   = (const float*)d_in[16];
    const float* b3   = (const float*)d_in[17];
    const float* W4   = (const float*)d_in[18];
    const float* b4   = (const float*)d_in[19];
    float* out = (float*)d_out;

    cudaFuncSetAttribute(disease_kernel,
                         cudaFuncAttributeMaxDynamicSharedMemorySize,
                         (int)sizeof(Smem));
    disease_kernel<<<128, NTHR, sizeof(Smem)>>>(
        xs, A, cell, Wg, bg, attn, Wt, bt, Wf, bf, Wf2, bf2,
        W1, b1, W2, b2, W3, b3, W4, b4, out);
}

// round 15
// speedup vs baseline: 1.0303x; 1.0303x over previous
#include <cuda_runtime.h>

namespace {

typedef unsigned long long u64;

constexpr int ATOM   = 34;
constexpr int HID    = 256;
constexpr int LATENT = 128;
constexpr int CELLS  = 512;
constexpr int NN     = 128;
constexpr int XPAD   = 36;
constexpr int HALF   = 64;
constexpr int DIN    = LATENT + CELLS;
constexpr int NTHR   = 512;
constexpr int NWARP  = 16;
constexpr float NEGV = -9e15f;

#define FMA2(d, a, b, c) asm("fma.rn.f32x2 %0, %1, %2, %3;" : "=l"(d) : "l"(a), "l"(b), "l"(c))

__device__ __forceinline__ u64 pack2(float lo, float hi) {
    u64 r; asm("mov.b64 %0, {%1, %2};" : "=l"(r) : "f"(lo), "f"(hi)); return r;
}
__device__ __forceinline__ float2 unpack2(u64 v) {
    float lo, hi; asm("mov.b64 {%0, %1}, %2;" : "=f"(lo), "=f"(hi) : "l"(v));
    return make_float2(lo, hi);
}
union F4U2 { float4 f4; struct { u64 lo, hi; } u; };

struct __align__(16) Smem {
    alignas(16) float2 WgP[3][17][32];     // (Wg[2k][l], Wg[2k+1][l])
    float Wgc[3][ATOM][2];                 // Wg columns 32,33
    float bg[3][ATOM];
    float attnv[3][2 * ATOM];
    alignas(16) float Wt[ATOM][HID];
    alignas(16) float bt[HID];
    alignas(16) float4 WfQ[HID / 4][32];   // (Wf[4p..4p+3][l])
    alignas(16) float Wfc32[HID];
    alignas(16) float Wfc33[HID];
    float bf[ATOM];
    alignas(16) float Wf2[ATOM][LATENT];
    alignas(16) float bf2[LATENT];
    alignas(16) float x[NN][XPAD];         // own rows updated in place (never peer-read)
    float xs0[HALF][ATOM];
    alignas(16) float hb[2][NN][XPAD];     // h, double-buffered by round parity
    float fsrc[2][NN];                     // round-parity buffered
    float fdst[2][NN];
    alignas(16) unsigned mask[HALF][4];
    union alignas(16) U {
        float attbuf[NWARP][NN][4];
        float gbuf[NWARP][2][HID];
    } u;
    alignas(16) float dvbuf[NWARP][2][36];
    alignas(16) float wmax[NWARP][LATENT];  // also MLP partial buffer
    float latloc[LATENT];
    float latpeer[LATENT];
    float vec[DIN];
    alignas(16) float h1[128];
    alignas(16) float h2[256];
    alignas(16) float h3own[256];
    float red[NWARP];
    float partial4;                         // written ONLY by rank1 via DSMEM
};

__device__ __forceinline__ float warp_sum(float v) {
    #pragma unroll
    for (int off = 16; off; off >>= 1)
        v += __shfl_xor_sync(0xffffffffu, v, off);
    return v;
}
__device__ __forceinline__ unsigned smem_u32(const void* p) {
    return (unsigned)__cvta_generic_to_shared(p);
}
__device__ __forceinline__ unsigned mapa_peer(unsigned local, unsigned rank) {
    unsigned r;
    asm("mapa.shared::cluster.u32 %0, %1, %2;" : "=r"(r) : "r"(local), "r"(rank));
    return r;
}
__device__ __forceinline__ void st_cluster_f32(unsigned addr, float v) {
    asm volatile("st.shared::cluster.f32 [%0], %1;" :: "r"(addr), "f"(v) : "memory");
}
__device__ __forceinline__ void st_cluster_u64(unsigned addr, u64 v) {
    asm volatile("st.shared::cluster.b64 [%0], %1;" :: "r"(addr), "l"(v) : "memory");
}
__device__ __forceinline__ void cluster_sync_() {
    asm volatile("barrier.cluster.arrive.aligned;" ::: "memory");
    asm volatile("barrier.cluster.wait.aligned;" ::: "memory");
}
__device__ __forceinline__ unsigned ctarank() {
    unsigned r;
    asm("mov.u32 %0, %%cluster_ctarank;" : "=r"(r));
    return r;
}

__global__ void __launch_bounds__(NTHR, 1) __cluster_dims__(2, 1, 1)
disease_kernel(const float* __restrict__ xs, const int* __restrict__ A,
               const float* __restrict__ cell,
               const float* __restrict__ Wg_g, const float* __restrict__ bg_g,
               const float* __restrict__ attn_g,
               const float* __restrict__ Wt_g, const float* __restrict__ bt_g,
               const float* __restrict__ Wf_g, const float* __restrict__ bf_g,
               const float* __restrict__ Wf2_g, const float* __restrict__ bf2_g,
               const float* __restrict__ W1, const float* __restrict__ b1,
               const float* __restrict__ W2, const float* __restrict__ b2,
               const float* __restrict__ W3, const float* __restrict__ b3,
               const float* __restrict__ W4, const float* __restrict__ b4,
               float* __restrict__ out)
{
    extern __shared__ char smem_raw[];
    Smem& s = *reinterpret_cast<Smem*>(smem_raw);
    const int b     = blockIdx.x >> 1;
    const unsigned rank = ctarank();
    const unsigned prk  = rank ^ 1u;
    const int own0  = (int)rank * HALF;
    const int tid   = threadIdx.x;
    const int lane  = tid & 31;
    const int w     = tid >> 5;

    const unsigned peer_h0  = mapa_peer(smem_u32(&s.hb[0][0][0]), prk);
    const unsigned peer_h1b = mapa_peer(smem_u32(&s.hb[1][0][0]), prk);
    const unsigned peer_fs0 = mapa_peer(smem_u32(&s.fsrc[0][0]), prk);
    const unsigned peer_fs1 = mapa_peer(smem_u32(&s.fsrc[1][0]), prk);
    const unsigned peer_fd0 = mapa_peer(smem_u32(&s.fdst[0][0]), prk);
    const unsigned peer_fd1 = mapa_peer(smem_u32(&s.fdst[1][0]), prk);
    const unsigned peer_lat = mapa_peer(smem_u32(&s.latpeer[0]), prk);

    // ---------- stage weights + inputs ----------
    for (int i = tid; i < 3 * 17 * 32; i += NTHR) {
        int r = i / (17 * 32), rem = i % (17 * 32), k = rem >> 5, l = rem & 31;
        s.WgP[r][k][l] = make_float2(Wg_g[r * ATOM * ATOM + (2 * k) * ATOM + l],
                                     Wg_g[r * ATOM * ATOM + (2 * k + 1) * ATOM + l]);
    }
    for (int i = tid; i < 3 * ATOM * 2; i += NTHR) {
        int r = i / (ATOM * 2), rem = i % (ATOM * 2), d = rem >> 1, c = rem & 1;
        s.Wgc[r][d][c] = Wg_g[r * ATOM * ATOM + d * ATOM + 32 + c];
    }
    for (int i = tid; i < 3 * ATOM; i += NTHR)        (&s.bg[0][0])[i]    = bg_g[i];
    for (int i = tid; i < 3 * 2 * ATOM; i += NTHR)    (&s.attnv[0][0])[i] = attn_g[i];
    for (int i = tid; i < (ATOM * HID) / 4; i += NTHR)
        reinterpret_cast<float4*>(&s.Wt[0][0])[i] =
            reinterpret_cast<const float4*>(Wt_g)[i];
    for (int i = tid; i < HID; i += NTHR)             s.bt[i]             = bt_g[i];
    for (int i = tid; i < (HID / 4) * 32; i += NTHR) {
        int p = i >> 5, l = i & 31;
        s.WfQ[p][l] = make_float4(Wf_g[(4 * p) * ATOM + l], Wf_g[(4 * p + 1) * ATOM + l],
                                  Wf_g[(4 * p + 2) * ATOM + l], Wf_g[(4 * p + 3) * ATOM + l]);
    }
    for (int i = tid; i < HID; i += NTHR) {
        s.Wfc32[i] = Wf_g[i * ATOM + 32];
        s.Wfc33[i] = Wf_g[i * ATOM + 33];
    }
    for (int i = tid; i < ATOM; i += NTHR)            s.bf[i]             = bf_g[i];
    for (int i = tid; i < (ATOM * LATENT) / 4; i += NTHR)
        reinterpret_cast<float4*>(&s.Wf2[0][0])[i] =
            reinterpret_cast<const float4*>(Wf2_g)[i];
    for (int i = tid; i < LATENT; i += NTHR)          s.bf2[i]            = bf2_g[i];
    for (int i = tid; i < NN * ATOM; i += NTHR) {
        int n = i / ATOM, d = i % ATOM;
        float v = xs[((size_t)b * NN + n) * ATOM + d];
        s.x[n][d] = v;
        if (n >= own0 && n < own0 + HALF) s.xs0[n - own0][d] = v;
    }

    // ---------- adjacency bitmask (own 64 rows) ----------
    {
        const int* __restrict__ Abase = A + (size_t)b * NN * NN;
        #pragma unroll
        for (int t = 0; t < 16; t++) {
            int widx  = w * 16 + t;
            int row   = widx >> 2;
            int chunk = widx & 3;
            int q     = chunk * 32 + lane;
            int av    = Abase[(own0 + row) * NN + q];
            unsigned word = __ballot_sync(0xffffffffu, av > 0);
            if (lane == 0) s.mask[row][chunk] = word;
        }
    }
    __syncthreads();

    // ---------- 3 GAT rounds; x in place, h/f parity-buffered ----------
    for (int r = 0; r < 3; r++) {
        const int par = r & 1;
        float (*hc)[XPAD] = s.hb[par];
        float* fsc = s.fsrc[par];
        float* fdc = s.fdst[par];
        const unsigned ph  = par ? peer_h1b : peer_h0;
        const unsigned pfs = par ? peer_fs1 : peer_fs0;
        const unsigned pfd = par ? peer_fd1 : peer_fd0;

        // h = relu(x @ Wg + bg): warp computes 4 OWN rows; mirror to peer.
        {
            u64 wgp[17];
            #pragma unroll
            for (int k = 0; k < 17; k++)
                wgp[k] = *reinterpret_cast<const u64*>(&s.WgP[r][k][lane]);
            const float bgl = s.bg[r][lane];
            const int n0 = own0 + 4 * w;
            #pragma unroll
            for (int j = 0; j < 4; j++) {
                const int n = n0 + j;
                u64 acc0 = pack2(bgl, 0.f);
                u64 acc1 = 0ull;
                #pragma unroll
                for (int db = 0; db < 8; db++) {
                    F4U2 xv; xv.f4 = *reinterpret_cast<const float4*>(&s.x[n][4 * db]);
                    FMA2(acc0, xv.u.lo, wgp[2 * db],     acc0);
                    FMA2(acc1, xv.u.hi, wgp[2 * db + 1], acc1);
                }
                u64 x2 = *reinterpret_cast<const u64*>(&s.x[n][32]);
                FMA2(acc0, x2, wgp[16], acc0);
                float2 a = unpack2(acc0), c = unpack2(acc1);
                float hv = fmaxf((a.x + a.y) + (c.x + c.y), 0.f);
                hc[n][lane] = hv;
                st_cluster_f32(ph + (unsigned)(n * XPAD + lane) * 4u, hv);
            }
        }
        // columns 32,33 mini-pass: own 64 rows (128 threads), mirrored
        if (tid < 128) {
            const int n = own0 + (tid >> 1), e = tid & 1;
            float a0 = s.bg[r][32 + e], a1 = 0.f;
            #pragma unroll
            for (int d = 0; d < ATOM; d += 2) {
                a0 += s.x[n][d]     * s.Wgc[r][d][e];
                a1 += s.x[n][d + 1] * s.Wgc[r][d + 1][e];
            }
            float hv = fmaxf(a0 + a1, 0.f);
            hc[n][32 + e] = hv;
            st_cluster_f32(ph + (unsigned)(n * XPAD + 32 + e) * 4u, hv);
        }
        __syncthreads();   // local h complete (fsrc below reads own-row h locally)

        // fsrc/fdst: own 64 rows (128 threads), mirrored
        if (tid < 128) {
            const int n = own0 + (tid >> 1), side = tid & 1;
            const float* av = &s.attnv[r][side * ATOM];
            float a0 = 0.f, a1 = 0.f;
            #pragma unroll
            for (int e = 0; e < ATOM; e += 2) {
                a0 += hc[n][e]     * av[e];
                a1 += hc[n][e + 1] * av[e + 1];
            }
            float fv = a0 + a1;
            if (side) {
                fdc[n] = fv;
                st_cluster_f32(pfd + (unsigned)n * 4u, fv);
            } else {
                fsc[n] = fv;
                st_cluster_f32(pfs + (unsigned)n * 4u, fv);
            }
        }
        // the ONLY cluster barrier this round: peer h + f delivered
        cluster_sync_();

        // softmax: 4 own rows per warp; no max-subtraction (exp-safe range),
        // masked entries exp(NEGV) underflow to exactly 0 as in reference.
        {
            float sc[4][4];
            #pragma unroll
            for (int rr = 0; rr < 4; rr++) {
                const int pl = w + 16 * rr;                 // local row
                const float fs = fsc[own0 + pl];
                uint4 mr = *reinterpret_cast<const uint4*>(&s.mask[pl][0]);
                const unsigned mw[4] = {mr.x, mr.y, mr.z, mr.w};
                #pragma unroll
                for (int j = 0; j < 4; j++) {
                    float e = fs + fdc[lane + 32 * j];
                    e = e > 0.f ? e : 0.01f * e;            // leaky_relu(0.01)
                    sc[rr][j] = ((mw[j] >> lane) & 1u) ? e : NEGV;
                }
            }
            float sum[4];
            #pragma unroll
            for (int rr = 0; rr < 4; rr++) {
                sum[rr] = 0.f;
                #pragma unroll
                for (int j = 0; j < 4; j++) {
                    sc[rr][j] = __expf(sc[rr][j]);          // reuse sc as weights
                    sum[rr] += sc[rr][j];
                }
            }
            #pragma unroll
            for (int off = 16; off; off >>= 1) {
                #pragma unroll
                for (int rr = 0; rr < 4; rr++)
                    sum[rr] += __shfl_xor_sync(0xffffffffu, sum[rr], off);
            }
            float inv[4];
            #pragma unroll
            for (int rr = 0; rr < 4; rr++) inv[rr] = 1.f / sum[rr];
            #pragma unroll
            for (int j = 0; j < 4; j++) {
                *reinterpret_cast<float4*>(&s.u.attbuf[w][lane + 32 * j][0]) =
                    make_float4(sc[0][j] * inv[0], sc[1][j] * inv[1],
                                sc[2][j] * inv[2], sc[3][j] * inv[3]);
            }
        }
        __syncwarp();

        // msg[d=lane] for 4 rows, f32x2, 4 accumulator chains
        u64 macc0 = 0ull, macc1 = 0ull, macc2 = 0ull, macc3 = 0ull;
        #pragma unroll 8
        for (int q = 0; q < NN; q += 2) {
            float hv0 = hc[q][lane];
            float hv1 = hc[q + 1][lane];
            F4U2 a0; a0.f4 = *reinterpret_cast<const float4*>(&s.u.attbuf[w][q][0]);
            F4U2 a1; a1.f4 = *reinterpret_cast<const float4*>(&s.u.attbuf[w][q + 1][0]);
            u64 hp0 = pack2(hv0, hv0), hp1 = pack2(hv1, hv1);
            FMA2(macc0, a0.u.lo, hp0, macc0);
            FMA2(macc1, a0.u.hi, hp0, macc1);
            FMA2(macc2, a1.u.lo, hp1, macc2);
            FMA2(macc3, a1.u.hi, hp1, macc3);
        }
        float2 mlo0 = unpack2(macc0), mhi0 = unpack2(macc1);
        float2 mlo1 = unpack2(macc2), mhi1 = unpack2(macc3);
        float m0[4] = {mlo0.x + mlo1.x, mlo0.y + mlo1.y,
                       mhi0.x + mhi1.x, mhi0.y + mhi1.y};

        // dims 32,33 partials — ONE interleaved 8-value warp reduction
        float mm[8] = {0.f, 0.f, 0.f, 0.f, 0.f, 0.f, 0.f, 0.f};
        #pragma unroll
        for (int j = 0; j < 4; j++) {
            int q = lane + 32 * j;
            float h32 = hc[q][32], h33 = hc[q][33];
            float4 a = *reinterpret_cast<const float4*>(&s.u.attbuf[w][q][0]);
            mm[0] += a.x * h32; mm[1] += a.y * h32; mm[2] += a.z * h32; mm[3] += a.w * h32;
            mm[4] += a.x * h33; mm[5] += a.y * h33; mm[6] += a.z * h33; mm[7] += a.w * h33;
        }
        #pragma unroll
        for (int off = 16; off; off >>= 1) {
            #pragma unroll
            for (int i = 0; i < 8; i++)
                mm[i] += __shfl_xor_sync(0xffffffffu, mm[i], off);
        }
        // in-place x update: own rows only (x is never read by the peer CTA)
        #pragma unroll
        for (int rr = 0; rr < 4; rr++) {
            const int p = own0 + w + 16 * rr;
            s.x[p][lane] += m0[rr];
            if (lane == 0) {
                s.x[p][32] += mm[rr];
                s.x[p][33] += mm[4 + rr];
            }
        }
        __syncthreads();   // local x updates visible CTA-wide for next round
    }

    // ---------- readout: 4 own rows per warp, 2 at a time, f32x2 ----------
    float rmax[4] = {-3.4e38f, -3.4e38f, -3.4e38f, -3.4e38f};
    const int rbase = own0 + 4 * w;
    #pragma unroll
    for (int bt2 = 0; bt2 < 2; bt2++) {
        const int rA = rbase + 2 * bt2;
        const int rB = rA + 1;
        const int e0 = 8 * lane;

        // g = relu(x@Wt+bt), 2 rows, lane owns 8 e's as 4 pairs
        u64 gAp[4], gBp[4];
        #pragma unroll
        for (int k = 0; k < 4; k++) {
            u64 btp = *reinterpret_cast<const u64*>(&s.bt[e0 + 2 * k]);
            gAp[k] = btp; gBp[k] = btp;
        }
        #pragma unroll
        for (int db = 0; db < 8; db++) {
            const int d = 4 * db;
            float4 xA = *reinterpret_cast<const float4*>(&s.x[rA][d]);
            float4 xB = *reinterpret_cast<const float4*>(&s.x[rB][d]);
            #pragma unroll
            for (int dd = 0; dd < 4; dd++) {
                F4U2 w0; w0.f4 = *reinterpret_cast<const float4*>(&s.Wt[d + dd][e0]);
                F4U2 w1; w1.f4 = *reinterpret_cast<const float4*>(&s.Wt[d + dd][e0 + 4]);
                u64 xap = pack2((&xA.x)[dd], (&xA.x)[dd]);
                u64 xbp = pack2((&xB.x)[dd], (&xB.x)[dd]);
                FMA2(gAp[0], w0.u.lo, xap, gAp[0]);
                FMA2(gAp[1], w0.u.hi, xap, gAp[1]);
                FMA2(gAp[2], w1.u.lo, xap, gAp[2]);
                FMA2(gAp[3], w1.u.hi, xap, gAp[3]);
                FMA2(gBp[0], w0.u.lo, xbp, gBp[0]);
                FMA2(gBp[1], w0.u.hi, xbp, gBp[1]);
                FMA2(gBp[2], w1.u.lo, xbp, gBp[2]);
                FMA2(gBp[3], w1.u.hi, xbp, gBp[3]);
            }
        }
        {
            float2 xA2 = *reinterpret_cast<const float2*>(&s.x[rA][32]);
            float2 xB2 = *reinterpret_cast<const float2*>(&s.x[rB][32]);
            #pragma unroll
            for (int dd = 0; dd < 2; dd++) {
                F4U2 w0; w0.f4 = *reinterpret_cast<const float4*>(&s.Wt[32 + dd][e0]);
                F4U2 w1; w1.f4 = *reinterpret_cast<const float4*>(&s.Wt[32 + dd][e0 + 4]);
                float xa = dd ? xA2.y : xA2.x;
                float xb = dd ? xB2.y : xB2.x;
                u64 xap = pack2(xa, xa), xbp = pack2(xb, xb);
                FMA2(gAp[0], w0.u.lo, xap, gAp[0]);
                FMA2(gAp[1], w0.u.hi, xap, gAp[1]);
                FMA2(gAp[2], w1.u.lo, xap, gAp[2]);
                FMA2(gAp[3], w1.u.hi, xap, gAp[3]);
                FMA2(gBp[0], w0.u.lo, xbp, gBp[0]);
                FMA2(gBp[1], w0.u.hi, xbp, gBp[1]);
                FMA2(gBp[2], w1.u.lo, xbp, gBp[2]);
                FMA2(gBp[3], w1.u.hi, xbp, gBp[3]);
            }
        }
        #pragma unroll
        for (int k = 0; k < 4; k++) {
            float2 ga = unpack2(gAp[k]);
            float2 gb = unpack2(gBp[k]);
            ga.x = fmaxf(ga.x, 0.f); ga.y = fmaxf(ga.y, 0.f);
            gb.x = fmaxf(gb.x, 0.f); gb.y = fmaxf(gb.y, 0.f);
            gAp[k] = pack2(ga.x, ga.y);
            gBp[k] = pack2(gb.x, gb.y);
            *reinterpret_cast<u64*>(&s.u.gbuf[w][0][e0 + 2 * k]) = gAp[k];
            *reinterpret_cast<u64*>(&s.u.gbuf[w][1][e0 + 2 * k]) = gBp[k];
        }
        __syncwarp();

        // dv[lane] = sum_e g[e]*Wf[e][lane], 2 rows, quad-packed Wf
        u64 dA0 = 0ull, dA1 = 0ull, dB0 = 0ull, dB1 = 0ull;
        #pragma unroll 8
        for (int e = 0; e < HID; e += 4) {
            F4U2 wf; wf.f4 = s.WfQ[e >> 2][lane];
            F4U2 ga; ga.f4 = *reinterpret_cast<const float4*>(&s.u.gbuf[w][0][e]);
            F4U2 gb; gb.f4 = *reinterpret_cast<const float4*>(&s.u.gbuf[w][1][e]);
            FMA2(dA0, ga.u.lo, wf.u.lo, dA0);
            FMA2(dA1, ga.u.hi, wf.u.hi, dA1);
            FMA2(dB0, gb.u.lo, wf.u.lo, dB0);
            FMA2(dB1, gb.u.hi, wf.u.hi, dB1);
        }
        float2 a0 = unpack2(dA0), a1 = unpack2(dA1);
        float2 c0 = unpack2(dB0), c1 = unpack2(dB1);
        float dvA = s.bf[lane] + s.xs0[rA - own0][lane] + ((a0.x + a0.y) + (a1.x + a1.y));
        float dvB = s.bf[lane] + s.xs0[rB - own0][lane] + ((c0.x + c0.y) + (c1.x + c1.y));

        // d[32], d[33] partials from register g (f32x2) — interleaved 4-sum
        u64 aA32 = 0ull, aA33 = 0ull, aB32 = 0ull, aB33 = 0ull;
        {
            F4U2 c32a; c32a.f4 = *reinterpret_cast<const float4*>(&s.Wfc32[e0]);
            F4U2 c32b; c32b.f4 = *reinterpret_cast<const float4*>(&s.Wfc32[e0 + 4]);
            F4U2 c33a; c33a.f4 = *reinterpret_cast<const float4*>(&s.Wfc33[e0]);
            F4U2 c33b; c33b.f4 = *reinterpret_cast<const float4*>(&s.Wfc33[e0 + 4]);
            u64 c32p[4] = {c32a.u.lo, c32a.u.hi, c32b.u.lo, c32b.u.hi};
            u64 c33p[4] = {c33a.u.lo, c33a.u.hi, c33b.u.lo, c33b.u.hi};
            #pragma unroll
            for (int k = 0; k < 4; k++) {
                FMA2(aA32, gAp[k], c32p[k], aA32);
                FMA2(aA33, gAp[k], c33p[k], aA33);
                FMA2(aB32, gBp[k], c32p[k], aB32);
                FMA2(aB33, gBp[k], c33p[k], aB33);
            }
        }
        float2 tA32 = unpack2(aA32), tA33 = unpack2(aA33);
        float2 tB32 = unpack2(aB32), tB33 = unpack2(aB33);
        float pA32 = tA32.x + tA32.y, pA33 = tA33.x + tA33.y;
        float pB32 = tB32.x + tB32.y, pB33 = tB33.x + tB33.y;
        #pragma unroll
        for (int off = 16; off; off >>= 1) {
            pA32 += __shfl_xor_sync(0xffffffffu, pA32, off);
            pA33 += __shfl_xor_sync(0xffffffffu, pA33, off);
            pB32 += __shfl_xor_sync(0xffffffffu, pB32, off);
            pB33 += __shfl_xor_sync(0xffffffffu, pB33, off);
        }
        s.dvbuf[w][0][lane] = dvA;
        s.dvbuf[w][1][lane] = dvB;
        if (lane == 0) {
            s.dvbuf[w][0][32] = pA32 + s.bf[32] + s.xs0[rA - own0][32];
            s.dvbuf[w][0][33] = pA33 + s.bf[33] + s.xs0[rA - own0][33];
            s.dvbuf[w][1][32] = pB32 + s.bf[32] + s.xs0[rB - own0][32];
            s.dvbuf[w][1][33] = pB33 + s.bf[33] + s.xs0[rB - own0][33];
        }
        __syncwarp();

        // latent = dv @ Wf2 + bf2, lane owns 4 latents (2 pairs), 2 rows
        {
            const int l0 = 4 * lane;
            u64 accA0 = *reinterpret_cast<const u64*>(&s.bf2[l0]);
            u64 accA1 = *reinterpret_cast<const u64*>(&s.bf2[l0 + 2]);
            u64 accB0 = accA0, accB1 = accA1;
            #pragma unroll
            for (int db = 0; db < 8; db++) {
                const int d = 4 * db;
                float4 dA4 = *reinterpret_cast<const float4*>(&s.dvbuf[w][0][d]);
                float4 dB4 = *reinterpret_cast<const float4*>(&s.dvbuf[w][1][d]);
                #pragma unroll
                for (int dd = 0; dd < 4; dd++) {
                    F4U2 wv; wv.f4 = *reinterpret_cast<const float4*>(&s.Wf2[d + dd][l0]);
                    u64 dap = pack2((&dA4.x)[dd], (&dA4.x)[dd]);
                    u64 dbp = pack2((&dB4.x)[dd], (&dB4.x)[dd]);
                    FMA2(accA0, wv.u.lo, dap, accA0);
                    FMA2(accA1, wv.u.hi, dap, accA1);
                    FMA2(accB0, wv.u.lo, dbp, accB0);
                    FMA2(accB1, wv.u.hi, dbp, accB1);
                }
            }
            {
                float2 dA2 = *reinterpret_cast<const float2*>(&s.dvbuf[w][0][32]);
                float2 dB2 = *reinterpret_cast<const float2*>(&s.dvbuf[w][1][32]);
                F4U2 w32; w32.f4 = *reinterpret_cast<const float4*>(&s.Wf2[32][l0]);
                F4U2 w33; w33.f4 = *reinterpret_cast<const float4*>(&s.Wf2[33][l0]);
                u64 a32p = pack2(dA2.x, dA2.x), a33p = pack2(dA2.y, dA2.y);
                u64 b32p = pack2(dB2.x, dB2.x), b33p = pack2(dB2.y, dB2.y);
                FMA2(accA0, w32.u.lo, a32p, accA0);
                FMA2(accA1, w32.u.hi, a32p, accA1);
                FMA2(accA0, w33.u.lo, a33p, accA0);
                FMA2(accA1, w33.u.hi, a33p, accA1);
                FMA2(accB0, w32.u.lo, b32p, accB0);
                FMA2(accB1, w32.u.hi, b32p, accB1);
                FMA2(accB0, w33.u.lo, b33p, accB0);
                FMA2(accB1, w33.u.hi, b33p, accB1);
            }
            float2 rA0 = unpack2(accA0), rA1 = unpack2(accA1);
            float2 rB0 = unpack2(accB0), rB1 = unpack2(accB1);
            rmax[0] = fmaxf(rmax[0], fmaxf(rA0.x, rB0.x));
            rmax[1] = fmaxf(rmax[1], fmaxf(rA0.y, rB0.y));
            rmax[2] = fmaxf(rmax[2], fmaxf(rA1.x, rB1.x));
            rmax[3] = fmaxf(rmax[3], fmaxf(rA1.y, rB1.y));
        }
        __syncwarp();
    }
    #pragma unroll
    for (int j = 0; j < 4; j++) s.wmax[w][4 * lane + j] = rmax[j];
    __syncthreads();

    // ---------- row-max combine + cluster exchange ----------
    if (tid < LATENT) {
        float m = s.wmax[0][tid];
        #pragma unroll
        for (int ww = 1; ww < NWARP; ww++) m = fmaxf(m, s.wmax[ww][tid]);
        s.latloc[tid] = m;
        st_cluster_f32(peer_lat + (unsigned)tid * 4u, m);
    }
    cluster_sync_();

    if (tid < LATENT) {
        float m = fmaxf(s.latloc[tid], s.latpeer[tid]);
        s.vec[tid] = 1.f / (1.f + __expf(-m));
    }
    for (int j = tid; j < CELLS; j += NTHR) {
        float c = cell[(size_t)b * CELLS + j];
        s.vec[LATENT + j] = 1.f / (1.f + __expf(-c));
    }
    __syncthreads();

    const unsigned peer_h1v = mapa_peer(smem_u32(&s.h1[0]), prk);
    const unsigned peer_h2v = mapa_peer(smem_u32(&s.h2[0]), prk);
    const unsigned peer_p4  = mapa_peer(smem_u32(&s.partial4), prk);
    float* wflat = &s.wmax[0][0];

    // ---------- MLP L1: 640 -> 128, own 64 outs as 32 pairs, 16 k-parts ----------
    {
        const int o2 = tid & 31, part = tid >> 5;
        const int og2 = (own0 >> 1) + o2;
        const int k0 = part * 40;
        u64 acc0 = 0ull, acc1 = 0ull, acc2 = 0ull, acc3 = 0ull;
        #pragma unroll 2
        for (int k = k0; k < k0 + 40; k += 4) {
            F4U2 vv; vv.f4 = *reinterpret_cast<const float4*>(&s.vec[k]);
            float2 vlo = unpack2(vv.u.lo), vhi = unpack2(vv.u.hi);
            u64 w0 = *reinterpret_cast<const u64*>(&W1[(size_t)k * 128 + 2 * og2]);
            u64 w1 = *reinterpret_cast<const u64*>(&W1[(size_t)(k + 1) * 128 + 2 * og2]);
            u64 w2 = *reinterpret_cast<const u64*>(&W1[(size_t)(k + 2) * 128 + 2 * og2]);
            u64 w3 = *reinterpret_cast<const u64*>(&W1[(size_t)(k + 3) * 128 + 2 * og2]);
            FMA2(acc0, w0, pack2(vlo.x, vlo.x), acc0);
            FMA2(acc1, w1, pack2(vlo.y, vlo.y), acc1);
            FMA2(acc2, w2, pack2(vhi.x, vhi.x), acc2);
            FMA2(acc3, w3, pack2(vhi.y, vhi.y), acc3);
        }
        float2 p0 = unpack2(acc0), p1 = unpack2(acc1);
        float2 p2 = unpack2(acc2), p3 = unpack2(acc3);
        *reinterpret_cast<float2*>(&wflat[part * 64 + 2 * o2]) =
            make_float2((p0.x + p1.x) + (p2.x + p3.x),
                        (p0.y + p1.y) + (p2.y + p3.y));
    }
    __syncthreads();
    if (tid < 32) {
        float2 v = *reinterpret_cast<const float2*>(&wflat[2 * tid]);
        #pragma unroll
        for (int p = 1; p < 16; p++) {
            float2 t = *reinterpret_cast<const float2*>(&wflat[p * 64 + 2 * tid]);
            v.x += t.x; v.y += t.y;
        }
        const int og = own0 + 2 * tid;
        v.x = fmaxf(v.x + b1[og], 0.f);
        v.y = fmaxf(v.y + b1[og + 1], 0.f);
        *reinterpret_cast<float2*>(&s.h1[og]) = v;
        st_cluster_u64(peer_h1v + (unsigned)og * 4u, pack2(v.x, v.y));
    }
    cluster_sync_();

    // ---------- MLP L2: 128 -> 256, own 128 outs as 64 pairs, 8 k-parts ----------
    {
        const int o2 = tid & 63, part = tid >> 6;
        const int og2 = (int)rank * 64 + o2;
        const int k0 = part * 16;
        u64 acc0 = 0ull, acc1 = 0ull;
        #pragma unroll 4
        for (int k = k0; k < k0 + 16; k += 2) {
            u64 w0 = *reinterpret_cast<const u64*>(&W2[(size_t)k * 256 + 2 * og2]);
            u64 w1 = *reinterpret_cast<const u64*>(&W2[(size_t)(k + 1) * 256 + 2 * og2]);
            FMA2(acc0, w0, pack2(s.h1[k], s.h1[k]), acc0);
            FMA2(acc1, w1, pack2(s.h1[k + 1], s.h1[k + 1]), acc1);
        }
        float2 p0 = unpack2(acc0), p1 = unpack2(acc1);
        *reinterpret_cast<float2*>(&wflat[part * 128 + 2 * o2]) =
            make_float2(p0.x + p1.x, p0.y + p1.y);
    }
    __syncthreads();
    if (tid < 64) {
        float2 v = *reinterpret_cast<const float2*>(&wflat[2 * tid]);
        #pragma unroll
        for (int p = 1; p < 8; p++) {
            float2 t = *reinterpret_cast<const float2*>(&wflat[p * 128 + 2 * tid]);
            v.x += t.x; v.y += t.y;
        }
        const int og = (int)rank * 128 + 2 * tid;
        v.x = fmaxf(v.x + b2[og], 0.f);
        v.y = fmaxf(v.y + b2[og + 1], 0.f);
        *reinterpret_cast<float2*>(&s.h2[og]) = v;
        st_cluster_u64(peer_h2v + (unsigned)og * 4u, pack2(v.x, v.y));
    }
    cluster_sync_();

    // ---------- MLP L3: 256 -> 512, own 256 outs as 128 pairs, 4 k-parts ----------
    {
        const int o2 = tid & 127, part = tid >> 7;
        const int og2 = (int)rank * 128 + o2;
        const int k0 = part * 64;
        u64 acc0 = 0ull, acc1 = 0ull;
        #pragma unroll 4
        for (int k = k0; k < k0 + 64; k += 2) {
            u64 w0 = *reinterpret_cast<const u64*>(&W3[(size_t)k * 512 + 2 * og2]);
            u64 w1 = *reinterpret_cast<const u64*>(&W3[(size_t)(k + 1) * 512 + 2 * og2]);
            FMA2(acc0, w0, pack2(s.h2[k], s.h2[k]), acc0);
            FMA2(acc1, w1, pack2(s.h2[k + 1], s.h2[k + 1]), acc1);
        }
        float2 p0 = unpack2(acc0), p1 = unpack2(acc1);
        *reinterpret_cast<float2*>(&wflat[part * 256 + 2 * o2]) =
            make_float2(p0.x + p1.x, p0.y + p1.y);
    }
    __syncthreads();
    if (tid < 128) {
        float2 v = *reinterpret_cast<const float2*>(&wflat[2 * tid]);
        #pragma unroll
        for (int p = 1; p < 4; p++) {
            float2 t = *reinterpret_cast<const float2*>(&wflat[p * 256 + 2 * tid]);
            v.x += t.x; v.y += t.y;
        }
        const int og = (int)rank * 256 + 2 * tid;
        v.x = fmaxf(v.x + b3[og], 0.f);
        v.y = fmaxf(v.y + b3[og + 1], 0.f);
        *reinterpret_cast<float2*>(&s.h3own[2 * tid]) = v;
    }
    __syncthreads();

    // ---------- MLP L4: 512 -> 1 ----------
    {
        float acc = 0.f;
        if (tid < 256) acc = s.h3own[tid] * W4[(int)rank * 256 + tid];
        acc = warp_sum(acc);
        if (lane == 0) s.red[w] = acc;
    }
    __syncthreads();
    if (rank == 1 && tid == 0) {
        float acc = 0.f;
        #pragma unroll
        for (int ww = 0; ww < 8; ww++) acc += s.red[ww];
        st_cluster_f32(peer_p4, acc);
    }
    cluster_sync_();
    if (rank == 0 && tid == 0) {
        float acc = 0.f;
        #pragma unroll
        for (int ww = 0; ww < 8; ww++) acc += s.red[ww];
        out[b] = acc + s.partial4 + b4[0];
    }
}

} // namespace

extern "C" void kernel_launch(void* const* d_in, const int* in_sizes, int n_in,
                              void* d_out, int out_size) {
    (void)in_sizes; (void)n_in; (void)out_size;
    const float* xs   = (const float*)d_in[0];
    const int*   A    = (const int*)d_in[1];
    const float* cell = (const float*)d_in[2];
    const float* Wg   = (const float*)d_in[3];
    const float* bg   = (const float*)d_in[4];
    const float* attn = (const float*)d_in[5];
    const float* Wt   = (const float*)d_in[6];
    const float* bt   = (const float*)d_in[7];
    const float* Wf   = (const float*)d_in[8];
    const float* bf   = (const float*)d_in[9];
    const float* Wf2  = (const float*)d_in[10];
    const float* bf2  = (const float*)d_in[11];
    const float* W1   = (const float*)d_in[12];
    const float* b1   = (const float*)d_in[13];
    const float* W2   = (const float*)d_in[14];
    const float* b2   = (const float*)d_in[15];
    const float* W3   = (const float*)d_in[16];
    const float* b3   = (const float*)d_in[17];
    const float* W4   = (const float*)d_in[18];
    const float* b4   = (const float*)d_in[19];
    float* out = (float*)d_out;

    cudaFuncSetAttribute(disease_kernel,
                         cudaFuncAttributeMaxDynamicSharedMemorySize,
                         (int)sizeof(Smem));
    disease_kernel<<<128, NTHR, sizeof(Smem)>>>(
        xs, A, cell, Wg, bg, attn, Wt, bt, Wf, bf, Wf2, bf2,
        W1, b1, W2, b2, W3, b3, W4, b4, out);
}